// round 10
// baseline (speedup 1.0000x reference)
#include <cuda_runtime.h>
#include <math.h>

// x[B=1024][T=8][V=4][D=8] fp32. Series s=(v*8+t) packed to g_xs[s][b][d].
// M = 1020. 28 pairs p = v*7+(t-1), t>=1; target series = (v,0).
#define B_N   1024
#define M_N   1020
#define RS    1024
#define N_PAIR 28
#define SENT  1e30f

__device__ float g_xs [32 * B_N * 8];
__device__ float g_WB [N_PAIR * M_N * RS];
__device__ float g_WC [4      * M_N * RS];
__device__ float g_WAC[4      * M_N * RS];
__device__ float g_part[N_PAIR * 128];
__device__ float g_psi[1040];

// ---------------- digamma table ------------------------------------------------------------
__global__ void psi_kernel() {
    int k = blockIdx.x * blockDim.x + threadIdx.x;
    if (k >= 1040) return;
    if (k == 0) { g_psi[0] = 0.f; return; }
    double s = 0.0;
    #pragma unroll
    for (int m = 0; m < 8; m++) s += 1.0 / (double)(k + m);
    double y = (double)k + 8.0;
    double inv = 1.0 / y, inv2 = inv * inv;
    double ps = log(y) - 0.5 * inv
              - inv2 * (1.0 / 12.0 - inv2 * (1.0 / 120.0 - inv2 * (1.0 / 252.0)));
    g_psi[k] = (float)(ps - s);
}

// ---------------- pack: coalesced read -> smem -> coalesced per-series write ---------------
#define PSTR 260
__global__ void pack_kernel(const float* __restrict__ x) {
    __shared__ float sm[16 * PSTR];
    int b0 = blockIdx.x * 16;
    for (int idx = threadIdx.x; idx < 1024; idx += 256) {
        int bl = idx >> 6, f = idx & 63;
        *(float4*)&sm[bl * PSTR + f * 4] = ((const float4*)x)[b0 * 64 + idx];
    }
    __syncthreads();
    #pragma unroll
    for (int k = 0; k < 4; k++) {
        int idx = threadIdx.x + k * 256;
        int s = idx >> 5;
        int q = idx & 31;
        int bl = q >> 1, h = q & 1;
        int t = s & 7, v = s >> 3;
        float4 val = *(float4*)&sm[bl * PSTR + (t * 8 + v * 2 + h) * 4];
        ((float4*)g_xs)[s * 2048 + (b0 + bl) * 2 + h] = val;
    }
}

// ---------------- fused E-tile + diagonal-window kernel ------------------------------------
// smem: sE persistent; sx (e-phase) and sW (W-phase) alias one buffer (never live together).
#define TS  64
#define TH  68
#define SEP 72   // 16B-aligned rows for LDS.128 window loads
#define SWP 65

__global__ void __launch_bounds__(256, 6) ew_kernel() {
    __shared__ float sE[TH * SEP];
    __shared__ __align__(16) char sbuf[TS * SWP * 4];   // max(sx 4352B, sW 16640B)
    float4* sxiA = (float4*)sbuf;          // [TH]
    float4* sxiB = sxiA + TH;
    float4* sxjA = sxiB + TH;
    float4* sxjB = sxjA + TH;
    float*  sW   = (float*)sbuf;           // [TS * SWP], aliases sx after e-phase

    int s = blockIdx.y;
    int t = s & 7, v = s >> 3;
    int tile = blockIdx.x;
    int ti = 0, rem = tile;
    while (rem >= 16 - ti) { rem -= 16 - ti; ti++; }
    int tj = ti + rem;
    int i0 = ti * TS, j0 = tj * TS;

    const float4* src = (const float4*)(g_xs + (size_t)s * (B_N * 8));
    if (threadIdx.x < TH) {
        int r  = threadIdx.x;
        int bi = min(i0 + r, B_N - 1);
        int bj = min(j0 + r, B_N - 1);
        sxiA[r] = src[bi * 2];     sxiB[r] = src[bi * 2 + 1];
        sxjA[r] = src[bj * 2];     sxjB[r] = src[bj * 2 + 1];
    }
    __syncthreads();

    int warp = threadIdx.x >> 5, lane = threadIdx.x & 31;
    // E tile: 17 groups of 4 rows over 8 warps
    for (int g = warp; g < 17; g += 8) {
        int ib = g * 4;
        float4 xa[4][2];
        #pragma unroll
        for (int r = 0; r < 4; r++) {
            xa[r][0] = sxiA[ib + r];
            xa[r][1] = sxiB[ib + r];
        }
        for (int jj = lane; jj < TH; jj += 32) {
            float4 ya = sxjA[jj];
            float4 yb = sxjB[jj];
            #pragma unroll
            for (int r = 0; r < 4; r++) {
                float m;
                m =          fabsf(xa[r][0].x - ya.x);
                m = fmaxf(m, fabsf(xa[r][0].y - ya.y));
                m = fmaxf(m, fabsf(xa[r][0].z - ya.z));
                m = fmaxf(m, fabsf(xa[r][0].w - ya.w));
                m = fmaxf(m, fabsf(xa[r][1].x - yb.x));
                m = fmaxf(m, fabsf(xa[r][1].y - yb.y));
                m = fmaxf(m, fabsf(xa[r][1].z - yb.z));
                m = fmaxf(m, fabsf(xa[r][1].w - yb.w));
                sE[(ib + r) * SEP + jj] = m;
            }
        }
    }
    __syncthreads();   // e-phase done: sx arrays dead, sW may now reuse the buffer

    int nstage = (t == 0) ? 2 : 1;
    for (int st = 0; st < nstage; st++) {
        float* out;
        if (t == 0) out = (st == 0 ? g_WC : g_WAC) + (size_t)v * (M_N * RS);
        else        out = g_WB + (size_t)(v * 7 + t - 1) * (M_N * RS);

        int iiw = threadIdx.x >> 4;
        int jj4 = (threadIdx.x & 15) * 4;
        #pragma unroll
        for (int it = 0; it < 4; it++) {
            int ii = iiw + it * 16;
            // load diagonal-window rows as aligned float4 pairs, extract shifted windows
            float e[5][8];
            #pragma unroll
            for (int r = 0; r < 5; r++) {
                if (r == 4 && st == 0) break;
                float4 f0 = *(const float4*)&sE[(ii + r) * SEP + jj4];
                float4 f1 = *(const float4*)&sE[(ii + r) * SEP + jj4 + 4];
                e[r][0] = f0.x; e[r][1] = f0.y; e[r][2] = f0.z; e[r][3] = f0.w;
                e[r][4] = f1.x; e[r][5] = f1.y; e[r][6] = f1.z; e[r][7] = f1.w;
            }
            float o[4];
            #pragma unroll
            for (int c = 0; c < 4; c++) {
                float m;
                m =          e[0][c    ];
                m = fmaxf(m, e[1][c + 1]);
                m = fmaxf(m, e[2][c + 2]);
                m = fmaxf(m, e[3][c + 3]);
                if (st == 1) m = fmaxf(m, e[4][c + 4]);
                o[c] = m;
                sW[ii * SWP + jj4 + c] = m;
            }
            int gi = i0 + ii;
            if (gi < M_N) {
                float4 q = (j0 + jj4 >= M_N)
                    ? make_float4(SENT, SENT, SENT, SENT)
                    : make_float4(o[0], o[1], o[2], o[3]);
                *(float4*)(out + (size_t)gi * RS + j0 + jj4) = q;
            }
        }
        __syncthreads();
        if (ti != tj) {
            int a  = threadIdx.x >> 4;
            int b4 = (threadIdx.x & 15) * 4;
            #pragma unroll
            for (int it = 0; it < 4; it++) {
                int aa = a + it * 16;
                int gj = j0 + aa;
                if (gj < M_N) {
                    float4 q = make_float4(
                        sW[(b4    ) * SWP + aa], sW[(b4 + 1) * SWP + aa],
                        sW[(b4 + 2) * SWP + aa], sW[(b4 + 3) * SWP + aa]);
                    *(float4*)(out + (size_t)gj * RS + i0 + b4) = q;
                }
            }
        }
        if (st + 1 < nstage) __syncthreads();
    }
}

// ---------------- branchless kNN + counts (round-7 te, verbatim) ---------------------------
__device__ __forceinline__ void ins4(float v, float& t0, float& t1, float& t2, float& t3) {
    float n0 = fminf(t0, v);
    float n1 = fminf(t1, fmaxf(t0, v));
    float n2 = fminf(t2, fmaxf(t1, v));
    float n3 = fminf(t3, fmaxf(t2, v));
    t0 = n0; t1 = n1; t2 = n2; t3 = n3;
}

__global__ void __launch_bounds__(256, 6) te_kernel() {
    int p = blockIdx.y;
    int v = p / 7;
    int warp = threadIdx.x >> 5, lane = threadIdx.x & 31;
    int i = blockIdx.x * 8 + warp;
    __shared__ float ws[8];
    float wrow = 0.f;
    if (i < M_N) {
        const float* wb  = g_WB  + (size_t)p * (M_N * RS) + (size_t)i * RS + lane * 4;
        const float* wac = g_WAC + (size_t)v * (M_N * RS) + (size_t)i * RS + lane * 4;
        const float* wc  = g_WC  + (size_t)v * (M_N * RS) + (size_t)i * RS + lane * 4;

        // pass 1: top-4 of dJ = max(WAC, WB); sentinels & self included (d(i,i)=0)
        float t0 = SENT, t1 = SENT, t2 = SENT, t3 = SENT;
        #pragma unroll 2
        for (int it = 0; it < 8; it++) {
            float4 b4 = *(const float4*)(wb + it * 128);
            float4 a4 = *(const float4*)(wac + it * 128);
            ins4(fmaxf(b4.x, a4.x), t0, t1, t2, t3);
            ins4(fmaxf(b4.y, a4.y), t0, t1, t2, t3);
            ins4(fmaxf(b4.z, a4.z), t0, t1, t2, t3);
            ins4(fmaxf(b4.w, a4.w), t0, t1, t2, t3);
        }
        #pragma unroll
        for (int off = 16; off > 0; off >>= 1) {
            float o0 = __shfl_xor_sync(0xffffffffu, t0, off);
            float o1 = __shfl_xor_sync(0xffffffffu, t1, off);
            float o2 = __shfl_xor_sync(0xffffffffu, t2, off);
            float o3 = __shfl_xor_sync(0xffffffffu, t3, off);
            ins4(o0, t0, t1, t2, t3); ins4(o1, t0, t1, t2, t3);
            ins4(o2, t0, t1, t2, t3); ins4(o3, t0, t1, t2, t3);
        }
        float eps = t3;   // 4th smallest incl. self == 3rd NN radius excl. self

        // pass 2: counts incl. self; max(b,c)<eps == (b<eps)&&(c<eps)
        int nA = 0, nB = 0, nC = 0;
        #pragma unroll 2
        for (int it = 0; it < 8; it++) {
            float4 b4 = *(const float4*)(wb + it * 128);
            float4 a4 = *(const float4*)(wac + it * 128);
            float4 c4 = *(const float4*)(wc + it * 128);
            int pcx = (c4.x < eps), pcy = (c4.y < eps),
                pcz = (c4.z < eps), pcw = (c4.w < eps);
            nC += pcx + pcy + pcz + pcw;
            nA += (a4.x < eps) + (a4.y < eps) + (a4.z < eps) + (a4.w < eps);
            nB += (pcx && (b4.x < eps)) + (pcy && (b4.y < eps))
                + (pcz && (b4.z < eps)) + (pcw && (b4.w < eps));
        }
        #pragma unroll
        for (int off = 16; off > 0; off >>= 1) {
            nA += __shfl_xor_sync(0xffffffffu, nA, off);
            nB += __shfl_xor_sync(0xffffffffu, nB, off);
            nC += __shfl_xor_sync(0xffffffffu, nC, off);
        }
        wrow = g_psi[nC] - g_psi[nA] - g_psi[nB];
    }
    if (lane == 0) ws[warp] = wrow;
    __syncthreads();
    if (threadIdx.x == 0) {
        float sum = 0.f;
        for (int k = 0; k < 8; k++) sum += ws[k];
        g_part[p * 128 + blockIdx.x] = sum;
    }
}

// ---------------- deterministic final reduction --------------------------------------------
__global__ void reduce_kernel(float* __restrict__ out) {
    __shared__ float sm[256];
    float s = 0.f;
    for (int idx = threadIdx.x; idx < N_PAIR * 128; idx += 256) s += g_part[idx];
    sm[threadIdx.x] = s;
    __syncthreads();
    if (threadIdx.x == 0) {
        float tot = 0.f;
        for (int k = 0; k < 256; k++) tot += sm[k];
        float psi3  = g_psi[3];
        float scale = 0.1f / 256.0f;               // BETA / (T*V*D)
        out[0] = scale * 0.25f * (28.0f * psi3 + tot / 1020.0f);
    }
}

extern "C" void kernel_launch(void* const* d_in, const int* in_sizes, int n_in,
                              void* d_out, int out_size) {
    const float* x = (const float*)d_in[0];
    float* out = (float*)d_out;
    psi_kernel   <<<5, 256>>>();
    pack_kernel  <<<64, 256>>>(x);
    ew_kernel    <<<dim3(136, 32), 256>>>();
    te_kernel    <<<dim3(128, 28), 256>>>();
    reduce_kernel<<<1, 256>>>(out);
}

// round 11
// speedup vs baseline: 1.2545x; 1.2545x over previous
#include <cuda_runtime.h>
#include <math.h>

// x[B=1024][T=8][V=4][D=8] fp32. Series s=(v*8+t) packed to g_xs[s][b][d].
// M = 1020. 28 pairs p = v*7+(t-1), t>=1; target series = (v,0).
#define B_N   1024
#define M_N   1020
#define RS    1024
#define N_PAIR 28
#define SENT  1e30f

__device__ float g_xs [32 * B_N * 8];
__device__ float g_WB [N_PAIR * M_N * RS];
__device__ float g_WC [4      * M_N * RS];
__device__ float g_WAC[4      * M_N * RS];
__device__ float g_part[N_PAIR * 128];
__device__ float g_psi[1040];

// ---------------- digamma table ------------------------------------------------------------
__global__ void psi_kernel() {
    int k = blockIdx.x * blockDim.x + threadIdx.x;
    if (k >= 1040) return;
    if (k == 0) { g_psi[0] = 0.f; return; }
    double s = 0.0;
    #pragma unroll
    for (int m = 0; m < 8; m++) s += 1.0 / (double)(k + m);
    double y = (double)k + 8.0;
    double inv = 1.0 / y, inv2 = inv * inv;
    double ps = log(y) - 0.5 * inv
              - inv2 * (1.0 / 12.0 - inv2 * (1.0 / 120.0 - inv2 * (1.0 / 252.0)));
    g_psi[k] = (float)(ps - s);
}

// ---------------- pack: coalesced read -> smem -> coalesced per-series write ---------------
#define PSTR 260
__global__ void pack_kernel(const float* __restrict__ x) {
    __shared__ float sm[16 * PSTR];
    int b0 = blockIdx.x * 16;
    for (int idx = threadIdx.x; idx < 1024; idx += 256) {
        int bl = idx >> 6, f = idx & 63;
        *(float4*)&sm[bl * PSTR + f * 4] = ((const float4*)x)[b0 * 64 + idx];
    }
    __syncthreads();
    #pragma unroll
    for (int k = 0; k < 4; k++) {
        int idx = threadIdx.x + k * 256;
        int s = idx >> 5;
        int q = idx & 31;
        int bl = q >> 1, h = q & 1;
        int t = s & 7, v = s >> 3;
        float4 val = *(float4*)&sm[bl * PSTR + (t * 8 + v * 2 + h) * 4];
        ((float4*)g_xs)[s * 2048 + (b0 + bl) * 2 + h] = val;
    }
}

// ---------------- fused E-tile + diagonal-window kernel (round-8 version) ------------------
#define TS  64
#define TH  68
#define SEP 72   // 16B-aligned rows for LDS.128 window loads
#define SWP 65

__global__ void __launch_bounds__(256) ew_kernel() {
    __shared__ float4 sxiA[TH], sxiB[TH], sxjA[TH], sxjB[TH];
    __shared__ float sE[TH * SEP];
    __shared__ float sW[TS * SWP];

    int s = blockIdx.y;
    int t = s & 7, v = s >> 3;
    int tile = blockIdx.x;
    int ti = 0, rem = tile;
    while (rem >= 16 - ti) { rem -= 16 - ti; ti++; }
    int tj = ti + rem;
    int i0 = ti * TS, j0 = tj * TS;

    const float4* src = (const float4*)(g_xs + (size_t)s * (B_N * 8));
    if (threadIdx.x < TH) {
        int r  = threadIdx.x;
        int bi = min(i0 + r, B_N - 1);
        int bj = min(j0 + r, B_N - 1);
        sxiA[r] = src[bi * 2];     sxiB[r] = src[bi * 2 + 1];
        sxjA[r] = src[bj * 2];     sxjB[r] = src[bj * 2 + 1];
    }
    __syncthreads();

    int warp = threadIdx.x >> 5, lane = threadIdx.x & 31;
    // E tile: 17 groups of 4 rows over 8 warps
    for (int g = warp; g < 17; g += 8) {
        int ib = g * 4;
        float4 xa[4][2];
        #pragma unroll
        for (int r = 0; r < 4; r++) {
            xa[r][0] = sxiA[ib + r];
            xa[r][1] = sxiB[ib + r];
        }
        for (int jj = lane; jj < TH; jj += 32) {
            float4 ya = sxjA[jj];
            float4 yb = sxjB[jj];
            #pragma unroll
            for (int r = 0; r < 4; r++) {
                float m;
                m =          fabsf(xa[r][0].x - ya.x);
                m = fmaxf(m, fabsf(xa[r][0].y - ya.y));
                m = fmaxf(m, fabsf(xa[r][0].z - ya.z));
                m = fmaxf(m, fabsf(xa[r][0].w - ya.w));
                m = fmaxf(m, fabsf(xa[r][1].x - yb.x));
                m = fmaxf(m, fabsf(xa[r][1].y - yb.y));
                m = fmaxf(m, fabsf(xa[r][1].z - yb.z));
                m = fmaxf(m, fabsf(xa[r][1].w - yb.w));
                sE[(ib + r) * SEP + jj] = m;
            }
        }
    }
    __syncthreads();

    int nstage = (t == 0) ? 2 : 1;
    for (int st = 0; st < nstage; st++) {
        float* out;
        if (t == 0) out = (st == 0 ? g_WC : g_WAC) + (size_t)v * (M_N * RS);
        else        out = g_WB + (size_t)(v * 7 + t - 1) * (M_N * RS);

        int iiw = threadIdx.x >> 4;
        int jj4 = (threadIdx.x & 15) * 4;
        #pragma unroll
        for (int it = 0; it < 4; it++) {
            int ii = iiw + it * 16;
            // load diagonal-window rows as aligned float4 pairs, extract shifted windows
            float e[5][8];
            #pragma unroll
            for (int r = 0; r < 5; r++) {
                if (r == 4 && st == 0) break;
                float4 f0 = *(const float4*)&sE[(ii + r) * SEP + jj4];
                float4 f1 = *(const float4*)&sE[(ii + r) * SEP + jj4 + 4];
                e[r][0] = f0.x; e[r][1] = f0.y; e[r][2] = f0.z; e[r][3] = f0.w;
                e[r][4] = f1.x; e[r][5] = f1.y; e[r][6] = f1.z; e[r][7] = f1.w;
            }
            float o[4];
            #pragma unroll
            for (int c = 0; c < 4; c++) {
                float m;
                m =          e[0][c    ];
                m = fmaxf(m, e[1][c + 1]);
                m = fmaxf(m, e[2][c + 2]);
                m = fmaxf(m, e[3][c + 3]);
                if (st == 1) m = fmaxf(m, e[4][c + 4]);
                o[c] = m;
                sW[ii * SWP + jj4 + c] = m;
            }
            int gi = i0 + ii;
            if (gi < M_N) {
                float4 q = (j0 + jj4 >= M_N)
                    ? make_float4(SENT, SENT, SENT, SENT)
                    : make_float4(o[0], o[1], o[2], o[3]);
                *(float4*)(out + (size_t)gi * RS + j0 + jj4) = q;
            }
        }
        __syncthreads();
        if (ti != tj) {
            int a  = threadIdx.x >> 4;
            int b4 = (threadIdx.x & 15) * 4;
            #pragma unroll
            for (int it = 0; it < 4; it++) {
                int aa = a + it * 16;
                int gj = j0 + aa;
                if (gj < M_N) {
                    float4 q = make_float4(
                        sW[(b4    ) * SWP + aa], sW[(b4 + 1) * SWP + aa],
                        sW[(b4 + 2) * SWP + aa], sW[(b4 + 3) * SWP + aa]);
                    *(float4*)(out + (size_t)gj * RS + i0 + b4) = q;
                }
            }
        }
        if (st + 1 < nstage) __syncthreads();
    }
}

// ---------------- branchless kNN + counts (round-7 te, verbatim) ---------------------------
__device__ __forceinline__ void ins4(float v, float& t0, float& t1, float& t2, float& t3) {
    float n0 = fminf(t0, v);
    float n1 = fminf(t1, fmaxf(t0, v));
    float n2 = fminf(t2, fmaxf(t1, v));
    float n3 = fminf(t3, fmaxf(t2, v));
    t0 = n0; t1 = n1; t2 = n2; t3 = n3;
}

__global__ void __launch_bounds__(256, 6) te_kernel() {
    int p = blockIdx.y;
    int v = p / 7;
    int warp = threadIdx.x >> 5, lane = threadIdx.x & 31;
    int i = blockIdx.x * 8 + warp;
    __shared__ float ws[8];
    float wrow = 0.f;
    if (i < M_N) {
        const float* wb  = g_WB  + (size_t)p * (M_N * RS) + (size_t)i * RS + lane * 4;
        const float* wac = g_WAC + (size_t)v * (M_N * RS) + (size_t)i * RS + lane * 4;
        const float* wc  = g_WC  + (size_t)v * (M_N * RS) + (size_t)i * RS + lane * 4;

        // pass 1: top-4 of dJ = max(WAC, WB); sentinels & self included (d(i,i)=0)
        float t0 = SENT, t1 = SENT, t2 = SENT, t3 = SENT;
        #pragma unroll 2
        for (int it = 0; it < 8; it++) {
            float4 b4 = *(const float4*)(wb + it * 128);
            float4 a4 = *(const float4*)(wac + it * 128);
            ins4(fmaxf(b4.x, a4.x), t0, t1, t2, t3);
            ins4(fmaxf(b4.y, a4.y), t0, t1, t2, t3);
            ins4(fmaxf(b4.z, a4.z), t0, t1, t2, t3);
            ins4(fmaxf(b4.w, a4.w), t0, t1, t2, t3);
        }
        #pragma unroll
        for (int off = 16; off > 0; off >>= 1) {
            float o0 = __shfl_xor_sync(0xffffffffu, t0, off);
            float o1 = __shfl_xor_sync(0xffffffffu, t1, off);
            float o2 = __shfl_xor_sync(0xffffffffu, t2, off);
            float o3 = __shfl_xor_sync(0xffffffffu, t3, off);
            ins4(o0, t0, t1, t2, t3); ins4(o1, t0, t1, t2, t3);
            ins4(o2, t0, t1, t2, t3); ins4(o3, t0, t1, t2, t3);
        }
        float eps = t3;   // 4th smallest incl. self == 3rd NN radius excl. self

        // pass 2: counts incl. self; max(b,c)<eps == (b<eps)&&(c<eps)
        int nA = 0, nB = 0, nC = 0;
        #pragma unroll 2
        for (int it = 0; it < 8; it++) {
            float4 b4 = *(const float4*)(wb + it * 128);
            float4 a4 = *(const float4*)(wac + it * 128);
            float4 c4 = *(const float4*)(wc + it * 128);
            int pcx = (c4.x < eps), pcy = (c4.y < eps),
                pcz = (c4.z < eps), pcw = (c4.w < eps);
            nC += pcx + pcy + pcz + pcw;
            nA += (a4.x < eps) + (a4.y < eps) + (a4.z < eps) + (a4.w < eps);
            nB += (pcx && (b4.x < eps)) + (pcy && (b4.y < eps))
                + (pcz && (b4.z < eps)) + (pcw && (b4.w < eps));
        }
        #pragma unroll
        for (int off = 16; off > 0; off >>= 1) {
            nA += __shfl_xor_sync(0xffffffffu, nA, off);
            nB += __shfl_xor_sync(0xffffffffu, nB, off);
            nC += __shfl_xor_sync(0xffffffffu, nC, off);
        }
        wrow = g_psi[nC] - g_psi[nA] - g_psi[nB];
    }
    if (lane == 0) ws[warp] = wrow;
    __syncthreads();
    if (threadIdx.x == 0) {
        float sum = 0.f;
        for (int k = 0; k < 8; k++) sum += ws[k];
        g_part[p * 128 + blockIdx.x] = sum;
    }
}

// ---------------- deterministic final reduction --------------------------------------------
__global__ void reduce_kernel(float* __restrict__ out) {
    __shared__ float sm[256];
    float s = 0.f;
    for (int idx = threadIdx.x; idx < N_PAIR * 128; idx += 256) s += g_part[idx];
    sm[threadIdx.x] = s;
    __syncthreads();
    if (threadIdx.x == 0) {
        float tot = 0.f;
        for (int k = 0; k < 256; k++) tot += sm[k];
        float psi3  = g_psi[3];
        float scale = 0.1f / 256.0f;               // BETA / (T*V*D)
        out[0] = scale * 0.25f * (28.0f * psi3 + tot / 1020.0f);
    }
}

extern "C" void kernel_launch(void* const* d_in, const int* in_sizes, int n_in,
                              void* d_out, int out_size) {
    const float* x = (const float*)d_in[0];
    float* out = (float*)d_out;
    psi_kernel   <<<5, 256>>>();
    pack_kernel  <<<64, 256>>>(x);
    ew_kernel    <<<dim3(136, 32), 256>>>();
    te_kernel    <<<dim3(128, 28), 256>>>();
    reduce_kernel<<<1, 256>>>(out);
}